// round 2
// baseline (speedup 1.0000x reference)
#include <cuda_runtime.h>

// CSPN 7x7 guided aggregation.
// O[b,y,x] = sum_{i,j} GW[b, i*7+j, y+3, x+3] * src[b, y+3-i, x+3-j]
//   src = h0 for center tap (i=j=3), else hn; zero outside [0,512)^2.
//
// Shapes: GW (8, 49, 518, 518) f32; hn,h0 (8,1,512,512) f32; out (8,1,512,512) f32.
// HBM-bound on the ~421 MB GW stream. Each block computes TWO adjacent output
// rows to double per-thread LDG MLP and amortize the hn halo.

#define H 512
#define W 512
#define HP 518            // H + K - 1
#define PLANE (518 * 518) // one guide plane

__global__ __launch_bounds__(512) void cspn_kernel(
    const float* __restrict__ gw,
    const float* __restrict__ hn,
    const float* __restrict__ h0,
    float* __restrict__ out)
{
    // 8 hn rows cover both output rows' 7-row neighborhoods:
    // s[r][c] = hn[b, y0-3+r, c-3], r in [0,8), zero out of bounds.
    __shared__ float s[8][520];

    const int x  = threadIdx.x;        // 0..511 output column
    const int y0 = blockIdx.x * 2;     // first of the two output rows
    const int b  = blockIdx.y;         // 0..7 batch

    const float* hnb = hn + (size_t)b * (H * W);

    // Cooperative halo load: 8 * 518 = 4144 elements by 512 threads.
    for (int idx = threadIdx.x; idx < 8 * HP; idx += 512) {
        const int r  = idx / HP;
        const int c  = idx - r * HP;
        const int yy = y0 - 3 + r;
        const int xx = c - 3;
        float v = 0.0f;
        if ((unsigned)yy < (unsigned)H && (unsigned)xx < (unsigned)W)
            v = hnb[yy * W + xx];
        s[r][c] = v;
    }
    __syncthreads();

    const size_t h0base = ((size_t)b * H + y0) * W + x;
    const float h0c0 = h0[h0base];
    const float h0c1 = h0[h0base + W];

    // Guide pointers at tap 0 for the two pixels (one row apart = HP floats).
    const float* g0 = gw + (size_t)b * 49 * PLANE
                         + (size_t)(y0 + 3) * HP + (x + 3);
    const float* g1 = g0 + HP;

    float acc0 = 0.0f;
    float acc1 = 0.0f;
    #pragma unroll
    for (int i = 0; i < 7; i++) {
        #pragma unroll
        for (int j = 0; j < 7; j++) {
            const int t = i * 7 + j;
            const size_t off = (size_t)t * PLANE;
            // Row y0   tap (i,j): hn[y0+3-i,   x+3-j] -> s[6-i][x+6-j]
            // Row y0+1 tap (i,j): hn[y0+4-i,   x+3-j] -> s[7-i][x+6-j]
            const float v0 = (t == 24) ? h0c0 : s[6 - i][x + 6 - j];
            const float v1 = (t == 24) ? h0c1 : s[7 - i][x + 6 - j];
            acc0 = fmaf(g0[off], v0, acc0);
            acc1 = fmaf(g1[off], v1, acc1);
        }
    }

    const size_t obase = ((size_t)b * H + y0) * W + x;
    out[obase]     = acc0;
    out[obase + W] = acc1;
}

extern "C" void kernel_launch(void* const* d_in, const int* in_sizes, int n_in,
                              void* d_out, int out_size)
{
    const float* gw = (const float*)d_in[0]; // guide_weight (8,49,518,518)
    const float* hn = (const float*)d_in[1]; // hn (8,1,512,512)
    const float* h0 = (const float*)d_in[2]; // h0 (8,1,512,512)
    float* out = (float*)d_out;

    dim3 grid(H / 2, 8, 1);   // (row-pair, batch)
    dim3 block(512, 1, 1);
    cspn_kernel<<<grid, block>>>(gw, hn, h0, out);
}

// round 8
// speedup vs baseline: 1.0112x; 1.0112x over previous
#include <cuda_runtime.h>

// CSPN 7x7 guided aggregation.
// O[b,y,x] = sum_{i,j} GW[b, i*7+j, y+3, x+3] * src[b, y+3-i, x+3-j]
//   src = h0 for center tap (i=j=3), else hn; zero outside [0,512)^2.
//
// Shapes: GW (8, 49, 518, 518) f32; hn,h0 (8,1,512,512) f32; out (8,1,512,512) f32.
// HBM-bound on the ~421 MB GW stream.
//
// Block = 256 threads = one row-pair x one 256-column half. The 49-tap loop is
// software-pipelined in 7-tap stages (14 LDGs per stage, double-buffered in
// registers). 256-thread blocks lift the ptxas register ceiling to 255 so the
// ~28 buffered floats + address registers fit WITHOUT spilling (a 512-thread
// block caps at 64 regs and would spill the double buffer).

#define H 512
#define W 512
#define HP 518            // H + K - 1
#define PLANE (518 * 518) // one guide plane
#define BX 256            // columns per block

__global__ __launch_bounds__(BX) void cspn_kernel(
    const float* __restrict__ gw,
    const float* __restrict__ hn,
    const float* __restrict__ h0,
    float* __restrict__ out)
{
    // 8 hn rows x (BX + 6) columns cover both output rows' neighborhoods:
    // s[r][c] = hn[b, y0-3+r, xbase + c - 3], zero out of bounds.
    __shared__ float s[8][BX + 8];

    const int tx    = threadIdx.x;        // 0..255 local column
    const int y0    = blockIdx.x * 2;     // first of the two output rows
    const int xbase = blockIdx.y * BX;    // 0 or 256
    const int b     = blockIdx.z;         // 0..7 batch
    const int x     = xbase + tx;         // global output column

    const float* hnb = hn + (size_t)b * (H * W);

    // Cooperative halo load: 8 * 262 = 2096 elements by 256 threads.
    for (int idx = tx; idx < 8 * (BX + 6); idx += BX) {
        const int r  = idx / (BX + 6);
        const int c  = idx - r * (BX + 6);
        const int yy = y0 - 3 + r;
        const int xx = xbase + c - 3;
        float v = 0.0f;
        if ((unsigned)yy < (unsigned)H && (unsigned)xx < (unsigned)W)
            v = hnb[yy * W + xx];
        s[r][c] = v;
    }
    __syncthreads();

    const size_t h0base = ((size_t)b * H + y0) * W + x;
    const float h0c0 = h0[h0base];
    const float h0c1 = h0[h0base + W];

    // Guide pointers at tap 0 for the two pixels (one row apart = HP floats).
    const float* g0 = gw + (size_t)b * 49 * PLANE
                         + (size_t)(y0 + 3) * HP + (x + 3);
    const float* g1 = g0 + HP;

    // Register double buffer: one stage = kernel row i = 7 taps x 2 out rows.
    float buf[2][14];

    // Prologue: load stage i=0.
    #pragma unroll
    for (int j = 0; j < 7; j++) {
        const size_t off = (size_t)j * PLANE;
        buf[0][2 * j]     = g0[off];
        buf[0][2 * j + 1] = g1[off];
    }

    float acc0 = 0.0f;
    float acc1 = 0.0f;

    #pragma unroll
    for (int i = 0; i < 7; i++) {
        const int cur = i & 1;
        const int nxt = cur ^ 1;

        // Issue next stage's 14 loads before consuming the current stage.
        if (i < 6) {
            #pragma unroll
            for (int j = 0; j < 7; j++) {
                const size_t off = (size_t)((i + 1) * 7 + j) * PLANE;
                buf[nxt][2 * j]     = g0[off];
                buf[nxt][2 * j + 1] = g1[off];
            }
        }

        // FMA current stage.
        #pragma unroll
        for (int j = 0; j < 7; j++) {
            const int t = i * 7 + j;
            // Row y0   tap (i,j): hn[y0+3-i, x+3-j] -> s[6-i][tx+6-j]
            // Row y0+1 tap (i,j): hn[y0+4-i, x+3-j] -> s[7-i][tx+6-j]
            const float v0 = (t == 24) ? h0c0 : s[6 - i][tx + 6 - j];
            const float v1 = (t == 24) ? h0c1 : s[7 - i][tx + 6 - j];
            acc0 = fmaf(buf[cur][2 * j],     v0, acc0);
            acc1 = fmaf(buf[cur][2 * j + 1], v1, acc1);
        }
    }

    const size_t obase = ((size_t)b * H + y0) * W + x;
    out[obase]     = acc0;
    out[obase + W] = acc1;
}

extern "C" void kernel_launch(void* const* d_in, const int* in_sizes, int n_in,
                              void* d_out, int out_size)
{
    const float* gw = (const float*)d_in[0]; // guide_weight (8,49,518,518)
    const float* hn = (const float*)d_in[1]; // hn (8,1,512,512)
    const float* h0 = (const float*)d_in[2]; // h0 (8,1,512,512)
    float* out = (float*)d_out;

    dim3 grid(H / 2, W / BX, 8);  // (row-pair, column-half, batch)
    dim3 block(BX, 1, 1);
    cspn_kernel<<<grid, block>>>(gw, hn, h0, out);
}